// round 7
// baseline (speedup 1.0000x reference)
#include <cuda_runtime.h>
#include <cuda_bf16.h>

// out = gelu_tanh(x) * gate,  gate = 1 + exp(log_alpha)*tanh(exp(log_sigma)*surp)
// surp = N/(2(N-1)) is data-independent (double argsort of distinct values per
// column is a permutation of 0..N-1 -> mean rank extremeness is constant).
//
// gelu via sigmoid identity + MUFU (ex2.approx, rcp.approx), rel err ~2^-22.
// Pure HBM-bound stream (268MB/pass); geometry tuned for latency hiding:
// 4 front-batched float4 loads per thread (MLP_p1=4), uniform L2 hints
// (evict_last loads / evict_first stores — best measured variant).

__device__ __forceinline__ float ex2_approx(float m) {
    float r;
    asm("ex2.approx.f32 %0, %1;" : "=f"(r) : "f"(m));
    return r;
}
__device__ __forceinline__ float rcp_approx(float d) {
    float r;
    asm("rcp.approx.f32 %0, %1;" : "=f"(r) : "f"(d));
    return r;
}

__device__ __forceinline__ unsigned long long mk_policy_evict_last() {
    unsigned long long p;
    asm("createpolicy.fractional.L2::evict_last.b64 %0, 1.0;" : "=l"(p));
    return p;
}
__device__ __forceinline__ unsigned long long mk_policy_evict_first() {
    unsigned long long p;
    asm("createpolicy.fractional.L2::evict_first.b64 %0, 1.0;" : "=l"(p));
    return p;
}

__device__ __forceinline__ float4 ld_hint4(const float4* p, unsigned long long pol) {
    float4 v;
    asm("ld.global.nc.L2::cache_hint.v4.f32 {%0,%1,%2,%3}, [%4], %5;"
        : "=f"(v.x), "=f"(v.y), "=f"(v.z), "=f"(v.w) : "l"(p), "l"(pol));
    return v;
}
__device__ __forceinline__ void st_hint4(float4* p, float4 v, unsigned long long pol) {
    asm("st.global.L2::cache_hint.v4.f32 [%0], {%1,%2,%3,%4}, %5;"
        :: "l"(p), "f"(v.x), "f"(v.y), "f"(v.z), "f"(v.w), "l"(pol));
}

// per-element: gate*x * sigmoid(2*c0*(x + c1*x^3))
__device__ __forceinline__ float gelu_fast(float x, float gate, float k0, float k1) {
    float x2 = x * x;
    float m  = x * fmaf(k1, x2, k0);
    float e  = ex2_approx(m);
    float r  = rcp_approx(e + 1.0f);
    return (gate * x) * r;
}

__device__ __forceinline__ float4 gelu_fast4(float4 v, float gate, float k0, float k1) {
    float4 r;
    r.x = gelu_fast(v.x, gate, k0, k1);
    r.y = gelu_fast(v.y, gate, k0, k1);
    r.z = gelu_fast(v.z, gate, k0, k1);
    r.w = gelu_fast(v.w, gate, k0, k1);
    return r;
}

__global__ void __launch_bounds__(256)
gelu_gate_kernel(const float4* __restrict__ x,
                 const float* __restrict__ log_alpha,
                 const float* __restrict__ log_sigma,
                 float4* __restrict__ out,
                 int n4, float surp) {
    constexpr float C0  = 0.7978845608028654f;   // sqrt(2/pi)
    constexpr float C1  = 0.044715f;
    constexpr float L2E = 1.4426950408889634f;
    const float k0 = -2.0f * C0 * L2E;
    const float k1 = k0 * C1;

    unsigned long long pol_ld = mk_policy_evict_last();
    unsigned long long pol_st = mk_policy_evict_first();

    // scalar gate (broadcast loads)
    float alpha = __expf(__ldg(log_alpha));
    float sigma = __expf(__ldg(log_sigma));
    float e2 = __expf(2.0f * sigma * surp);
    float gate = fmaf(alpha, __fdividef(e2 - 1.0f, e2 + 1.0f), 1.0f);

    // four float4 per thread, all loads front-batched (MLP_p1=4),
    // stride-256 so each of the 4 accesses is warp-coalesced
    int base = blockIdx.x * (4 * 256) + threadIdx.x;
    int i0 = base;
    int i1 = base + 256;
    int i2 = base + 512;
    int i3 = base + 768;

    if (i3 < n4) {
        float4 v0 = ld_hint4(x + i0, pol_ld);   // all four in flight before use
        float4 v1 = ld_hint4(x + i1, pol_ld);
        float4 v2 = ld_hint4(x + i2, pol_ld);
        float4 v3 = ld_hint4(x + i3, pol_ld);
        st_hint4(out + i0, gelu_fast4(v0, gate, k0, k1), pol_st);
        st_hint4(out + i1, gelu_fast4(v1, gate, k0, k1), pol_st);
        st_hint4(out + i2, gelu_fast4(v2, gate, k0, k1), pol_st);
        st_hint4(out + i3, gelu_fast4(v3, gate, k0, k1), pol_st);
    } else {
        // generic tail (not hit at the benchmarked shape: n4 % 1024 == 0)
        #pragma unroll
        for (int k = 0; k < 4; k++) {
            int i = base + k * 256;
            if (i < n4) {
                float4 v = ld_hint4(x + i, pol_ld);
                st_hint4(out + i, gelu_fast4(v, gate, k0, k1), pol_st);
            }
        }
    }
}

extern "C" void kernel_launch(void* const* d_in, const int* in_sizes, int n_in,
                              void* d_out, int out_size) {
    const float* x         = (const float*)d_in[0];
    const float* log_alpha = (const float*)d_in[1];
    const float* log_sigma = (const float*)d_in[2];
    float* out = (float*)d_out;

    int n = in_sizes[0];            // B*T*D elements
    const int D = 4096;
    int N_tokens = n / D;           // 8192
    float surp = (float)N_tokens / (2.0f * (float)(N_tokens - 1));

    int n4 = n / 4;                 // multiple of 4 (D = 4096)
    int threads = 256;
    int elems_per_block = threads * 4;
    int blocks = (n4 + elems_per_block - 1) / elems_per_block;
    gelu_gate_kernel<<<blocks, threads>>>(
        (const float4*)x, log_alpha, log_sigma, (float4*)out, n4, surp);
}

// round 8
// speedup vs baseline: 1.0375x; 1.0375x over previous
#include <cuda_runtime.h>
#include <cuda_bf16.h>

// out = gelu_tanh(x) * gate,  gate = 1 + exp(log_alpha)*tanh(exp(log_sigma)*surp)
// surp = N/(2(N-1)) is data-independent (double argsort of distinct values per
// column is a permutation of 0..N-1 -> mean rank extremeness is constant).
//
// gelu via sigmoid identity + MUFU (ex2.approx, rcp.approx), rel err ~2^-22.
//
// Converged config: pure HBM-bound stream at ~7.3 TB/s combined (~91% of
// spec). MLP=2 front-batched float4 loads (best measured), uniform L2 hints
// (evict_last loads / evict_first stores), 512-thread blocks.

__device__ __forceinline__ float ex2_approx(float m) {
    float r;
    asm("ex2.approx.f32 %0, %1;" : "=f"(r) : "f"(m));
    return r;
}
__device__ __forceinline__ float rcp_approx(float d) {
    float r;
    asm("rcp.approx.f32 %0, %1;" : "=f"(r) : "f"(d));
    return r;
}

__device__ __forceinline__ unsigned long long mk_policy_evict_last() {
    unsigned long long p;
    asm("createpolicy.fractional.L2::evict_last.b64 %0, 1.0;" : "=l"(p));
    return p;
}
__device__ __forceinline__ unsigned long long mk_policy_evict_first() {
    unsigned long long p;
    asm("createpolicy.fractional.L2::evict_first.b64 %0, 1.0;" : "=l"(p));
    return p;
}

__device__ __forceinline__ float4 ld_hint4(const float4* p, unsigned long long pol) {
    float4 v;
    asm("ld.global.nc.L2::cache_hint.v4.f32 {%0,%1,%2,%3}, [%4], %5;"
        : "=f"(v.x), "=f"(v.y), "=f"(v.z), "=f"(v.w) : "l"(p), "l"(pol));
    return v;
}
__device__ __forceinline__ void st_hint4(float4* p, float4 v, unsigned long long pol) {
    asm("st.global.L2::cache_hint.v4.f32 [%0], {%1,%2,%3,%4}, %5;"
        :: "l"(p), "f"(v.x), "f"(v.y), "f"(v.z), "f"(v.w), "l"(pol));
}

// per-element: gate*x * sigmoid(2*c0*(x + c1*x^3))
//   m = x * fma(k1, x*x, k0), k0 = -2*c0*log2e, k1 = k0*c1
//   out = gate*x * rcp(1 + exp2(m))
__device__ __forceinline__ float gelu_fast(float x, float gate, float k0, float k1) {
    float x2 = x * x;
    float m  = x * fmaf(k1, x2, k0);
    float e  = ex2_approx(m);
    float r  = rcp_approx(e + 1.0f);
    return (gate * x) * r;
}

__device__ __forceinline__ float4 gelu_fast4(float4 v, float gate, float k0, float k1) {
    float4 r;
    r.x = gelu_fast(v.x, gate, k0, k1);
    r.y = gelu_fast(v.y, gate, k0, k1);
    r.z = gelu_fast(v.z, gate, k0, k1);
    r.w = gelu_fast(v.w, gate, k0, k1);
    return r;
}

__global__ void __launch_bounds__(512)
gelu_gate_kernel(const float4* __restrict__ x,
                 const float* __restrict__ log_alpha,
                 const float* __restrict__ log_sigma,
                 float4* __restrict__ out,
                 int n4, float surp) {
    constexpr float C0  = 0.7978845608028654f;   // sqrt(2/pi)
    constexpr float C1  = 0.044715f;
    constexpr float L2E = 1.4426950408889634f;
    const float k0 = -2.0f * C0 * L2E;
    const float k1 = k0 * C1;

    unsigned long long pol_ld = mk_policy_evict_last();
    unsigned long long pol_st = mk_policy_evict_first();

    // scalar gate (broadcast loads)
    float alpha = __expf(__ldg(log_alpha));
    float sigma = __expf(__ldg(log_sigma));
    float e2 = __expf(2.0f * sigma * surp);
    float gate = fmaf(alpha, __fdividef(e2 - 1.0f, e2 + 1.0f), 1.0f);

    // two float4 per thread, front-batched (MLP=2), warp-coalesced pairs
    int base = blockIdx.x * (2 * 512) + threadIdx.x;
    int i0 = base;
    int i1 = base + 512;

    if (i1 < n4) {
        float4 v0 = ld_hint4(x + i0, pol_ld);   // both loads in flight before use
        float4 v1 = ld_hint4(x + i1, pol_ld);
        st_hint4(out + i0, gelu_fast4(v0, gate, k0, k1), pol_st);
        st_hint4(out + i1, gelu_fast4(v1, gate, k0, k1), pol_st);
    } else {
        if (i0 < n4) {                          // generic tail (unused at bench shape)
            float4 v0 = ld_hint4(x + i0, pol_ld);
            st_hint4(out + i0, gelu_fast4(v0, gate, k0, k1), pol_st);
        }
    }
}

extern "C" void kernel_launch(void* const* d_in, const int* in_sizes, int n_in,
                              void* d_out, int out_size) {
    const float* x         = (const float*)d_in[0];
    const float* log_alpha = (const float*)d_in[1];
    const float* log_sigma = (const float*)d_in[2];
    float* out = (float*)d_out;

    int n = in_sizes[0];            // B*T*D elements
    const int D = 4096;
    int N_tokens = n / D;           // 8192
    float surp = (float)N_tokens / (2.0f * (float)(N_tokens - 1));

    int n4 = n / 4;                 // multiple of 4 (D = 4096)
    int threads = 512;
    int elems_per_block = threads * 2;
    int blocks = (n4 + elems_per_block - 1) / elems_per_block;
    gelu_gate_kernel<<<blocks, threads>>>(
        (const float4*)x, log_alpha, log_sigma, (float4*)out, n4, surp);
}